// round 8
// baseline (speedup 1.0000x reference)
#include <cuda_runtime.h>
#include <cuda_bf16.h>
#include <math.h>
#include <stdint.h>

#define MAXT 4096
#define D_BB 768
#define KPAD 960          // 160 feat(+pad) + 768 bb + 32 pad
#define CH   64           // k per chunk
#define NCH  15           // total chunks (kq0: 0..8, kq1: 8..15)
#define NSTG 2            // smem pipeline stages
#define BUFB 40960        // per stage: Ah 4K | Al 4K | Bh 16K | Bl 16K
#define SMEM_TOTAL (NSTG * BUFB)

typedef unsigned long long u64;
typedef unsigned int       u32;

__device__ __align__(16) __nv_bfloat16 g_Bh[128 * KPAD];
__device__ __align__(16) __nv_bfloat16 g_Bl[128 * KPAD];
__device__ float g_part[2 * MAXT * 128];   // raw D partials per K-half
__device__ int   g_cnt[128];               // per-tile arrival counters

// ---- helpers -----------------------------------------------------------------
__device__ __forceinline__ u32 smem_u32(const void* p) {
    u32 a;
    asm("{ .reg .u64 t; cvta.to.shared.u64 t, %1; cvt.u32.u64 %0, t; }"
        : "=r"(a) : "l"(p));
    return a;
}
__device__ __forceinline__ u32 SWZ(u32 b) { return b ^ ((b >> 3) & 0x70); }

__device__ __forceinline__ u32 pack_bf2(float lo, float hi) {
    __nv_bfloat162 v = __floats2bfloat162_rn(lo, hi);
    return *(u32*)&v;
}
__device__ __forceinline__ float bfr(float x) {
    return __bfloat162float(__float2bfloat16_rn(x));
}

#define LDMX4(r, addr) \
    asm volatile("ldmatrix.sync.aligned.m8n8.x4.shared.b16 {%0,%1,%2,%3}, [%4];" \
        : "=r"((r)[0]), "=r"((r)[1]), "=r"((r)[2]), "=r"((r)[3]) : "r"(addr))

#define MMA16816(d, a, b0, b1) \
    asm volatile("mma.sync.aligned.m16n8k16.row.col.f32.bf16.bf16.f32 " \
        "{%0,%1,%2,%3}, {%4,%5,%6,%7}, {%8,%9}, {%0,%1,%2,%3};" \
        : "+f"((d)[0]), "+f"((d)[1]), "+f"((d)[2]), "+f"((d)[3]) \
        : "r"((a)[0]), "r"((a)[1]), "r"((a)[2]), "r"((a)[3]), "r"(b0), "r"(b1))

#define CPA16(dst, src) \
    asm volatile("cp.async.cg.shared.global [%0], [%1], 16;" \
        :: "r"(dst), "l"(src) : "memory")
#define CPA_COMMIT() asm volatile("cp.async.commit_group;" ::: "memory")
#define CPA_WAIT(n)  asm volatile("cp.async.wait_group %0;" :: "n"(n) : "memory")

#define STS64(r0, r1, sa) \
    asm volatile("st.shared.v2.b32 [%0], {%1, %2};" \
        :: "r"(sa), "r"(r0), "r"(r1) : "memory")

// -----------------------------------------------------------------------------
// Prep: W1 [918,128] fp32 -> g_Bh/g_Bl [128 n][960 k] bf16 split (row remap).
// -----------------------------------------------------------------------------
__global__ void prep_B(const float* __restrict__ W1) {
    int id = blockIdx.x * 256 + threadIdx.x;        // 128 n * 240 groups of 4
    if (id >= 128 * 240) return;
    int n  = id / 240;
    int k4 = (id % 240) * 4;
    u32 hw[2], lw[2];
    #pragma unroll
    for (int p = 0; p < 2; p++) {
        float v0 = 0.f, v1 = 0.f;
        int g0 = k4 + p * 2, g1 = g0 + 1;
        if (g0 < 150)                    v0 = W1[(size_t)g0 * 128 + n];
        else if (g0 >= 160 && g0 < 928)  v0 = W1[(size_t)(g0 - 10) * 128 + n];
        if (g1 < 150)                    v1 = W1[(size_t)g1 * 128 + n];
        else if (g1 >= 160 && g1 < 928)  v1 = W1[(size_t)(g1 - 10) * 128 + n];
        float h0 = bfr(v0), h1 = bfr(v1);
        hw[p] = pack_bf2(v0, v1);
        lw[p] = pack_bf2(v0 - h0, v1 - h1);
    }
    *(u64*)&g_Bh[(size_t)n * KPAD + k4] = (u64)hw[0] | ((u64)hw[1] << 32);
    *(u64*)&g_Bl[(size_t)n * KPAD + k4] = (u64)lw[0] | ((u64)lw[1] << 32);
}

// -----------------------------------------------------------------------------
// GEMM: grid (T/32, 2). 512 threads, 16 warps (2M x 8N). K-split in half;
// both halves store raw D to g_part; last-arriving CTA per tile does epilogue.
// -----------------------------------------------------------------------------
__global__ void __launch_bounds__(512, 2)
critic_mma(const float* __restrict__ bb,
           const float* __restrict__ res,   const float* __restrict__ fr,
           const float* __restrict__ estep, const float* __restrict__ enode,
           const float* __restrict__ ccl,   const float* __restrict__ cnd,
           const float* __restrict__ b1,
           const float* __restrict__ W3, const float* __restrict__ b3,
           const float* __restrict__ W4, const float* __restrict__ b4,
           const float* __restrict__ W5, const float* __restrict__ b5,
           const float* __restrict__ W6, const float* __restrict__ b6,
           float* __restrict__ out, int T)
{
    extern __shared__ __align__(16) char dsm[];
    __shared__ int winflag;
    const u32 sb = smem_u32(dsm);

    const int tid  = threadIdx.x;
    const int lane = tid & 31;
    const int wid  = tid >> 5;
    const int mtile = blockIdx.x;
    const int kq    = blockIdx.y;
    const int mbase = mtile * 32;
    const int cbeg  = kq ? 8 : 0;
    const int cend  = kq ? NCH : 8;

    const int m0w = (wid & 1) * 16;
    const int n0w = (wid >> 1) * 16;

    // ---- A loader mapping: thread -> (row, 4 consecutive k) ----
    const int ar = tid >> 4;
    const int ak = (tid & 15) * 4;
    int atask = mbase + ar; if (atask >= T) atask = T - 1;
    const float* bbrow = bb + (size_t)atask * D_BB;
    const u32 aoff = SWZ((u32)(ar * 128 + ak * 2));

    // ---- B loader mapping ----
    int brow[2], bseg[2]; u32 bdst[2];
    #pragma unroll
    for (int i = 0; i < 2; i++) {
        int id = tid + i * 512;
        brow[i] = id >> 3;
        bseg[i] = id & 7;
        bdst[i] = SWZ((u32)(brow[i] * 128 + bseg[i] * 16));
    }

    // ---- fragment address bases ----
    const u32 aRowByte = (u32)((m0w + (lane & 7) + ((lane >> 3) & 1) * 8) * 128
                               + (lane >> 4) * 16);
    const u32 bRowByte = (u32)((n0w + (lane >> 4) * 8 + (lane & 7)) * 128
                               + ((lane >> 3) & 1) * 16);

    float Da[2][4], Db[2][4], Dc[2][4];
    #pragma unroll
    for (int h = 0; h < 2; h++)
        #pragma unroll
        for (int j = 0; j < 4; j++) { Da[h][j] = 0.f; Db[h][j] = 0.f; Dc[h][j] = 0.f; }

    auto loadA = [&](int c, float* x) {
        int g0 = c * CH + ak;
        if (g0 >= 160 && g0 + 4 <= 928) {
            float4 v = *(const float4*)(bbrow + (g0 - 160));
            x[0] = v.x; x[1] = v.y; x[2] = v.z; x[3] = v.w;
        } else {
            #pragma unroll
            for (int j = 0; j < 4; j++) {
                int gk = g0 + j;
                float v = 0.f;
                if (gk < 150) {
                    int nn = gk / 30, rem = gk - nn * 30;
                    int mm = rem / 6, oo = rem - mm * 6;
                    v = res[atask * 5 + nn] * fr[atask * 5 + mm] * estep[atask * 6 + oo];
                } else if (gk >= 160 && gk < 928) {
                    v = bbrow[gk - 160];
                }
                x[j] = v;
            }
        }
    };
    auto storeA = [&](int c, const float* x) {
        const u32 base = sb + (u32)(c % NSTG) * BUFB;
        float h0 = bfr(x[0]), h1 = bfr(x[1]), h2 = bfr(x[2]), h3 = bfr(x[3]);
        STS64(pack_bf2(x[0], x[1]), pack_bf2(x[2], x[3]), base + aoff);
        STS64(pack_bf2(x[0] - h0, x[1] - h1), pack_bf2(x[2] - h2, x[3] - h3),
              base + 4096 + aoff);
    };
    auto issueB = [&](int c) {
        const u32 base = sb + (u32)(c % NSTG) * BUFB;
        #pragma unroll
        for (int i = 0; i < 2; i++) {
            const size_t so = (size_t)brow[i] * KPAD + c * CH + bseg[i] * 8;
            CPA16(base + 8192  + bdst[i], g_Bh + so);
            CPA16(base + 24576 + bdst[i], g_Bl + so);
        }
    };
    auto compute = [&](int c) {
        const u32 base = sb + (u32)(c % NSTG) * BUFB;
        const u32 sAh = base, sAl = base + 4096, sBh = base + 8192, sBl = base + 24576;
        #pragma unroll
        for (int ks = 0; ks < 4; ks++) {
            const u32 ao = SWZ(aRowByte + ks * 32);
            const u32 bo = SWZ(bRowByte + ks * 32);
            u32 a_h[4], a_l[4], b_h[4], b_l[4];
            LDMX4(a_h, sAh + ao);
            LDMX4(b_h, sBh + bo);
            LDMX4(a_l, sAl + ao);
            LDMX4(b_l, sBl + bo);
            MMA16816(Da[0], a_h, b_h[0], b_h[1]);
            MMA16816(Db[0], a_h, b_l[0], b_l[1]);
            MMA16816(Dc[0], a_l, b_h[0], b_h[1]);
            MMA16816(Da[1], a_h, b_h[2], b_h[3]);
            MMA16816(Db[1], a_h, b_l[2], b_l[3]);
            MMA16816(Dc[1], a_l, b_h[2], b_h[3]);
        }
    };

    // ---- prologue: stages cbeg, cbeg+1; hold A(cbeg+2) in regs ----
    {
        float x0[4];
        loadA(cbeg, x0);     storeA(cbeg, x0);     issueB(cbeg);     CPA_COMMIT();
        loadA(cbeg + 1, x0); storeA(cbeg + 1, x0); issueB(cbeg + 1); CPA_COMMIT();
    }
    float xh[4];
    loadA(cbeg + 2, xh);
    CPA_WAIT(1);
    __syncthreads();

    // ---- main loop: double buffer, 2 syncs/chunk ----
    for (int c = cbeg; c < cend; c++) {
        compute(c);
        __syncthreads();                       // stage c%2 free
        if (c + 2 < cend) {
            storeA(c + 2, xh);                 // stage (c+2)%2 == c%2
            if (c + 3 < cend) loadA(c + 3, xh);
            issueB(c + 2); CPA_COMMIT();
            CPA_WAIT(1);                       // B(c+1) arrived
        } else if (c + 1 < cend) {
            CPA_WAIT(0);
        }
        __syncthreads();
    }

    // ---- store raw D partials to g_part[kq] ----
    {
        float* slab = g_part + (size_t)kq * MAXT * 128;
        const int drow = m0w + (lane >> 2);
        #pragma unroll
        for (int h = 0; h < 2; h++) {
            int col = n0w + h * 8 + 2 * (lane & 3);
            float d0 = Da[h][0] + Db[h][0] + Dc[h][0];
            float d1 = Da[h][1] + Db[h][1] + Dc[h][1];
            float d2 = Da[h][2] + Db[h][2] + Dc[h][2];
            float d3 = Da[h][3] + Db[h][3] + Dc[h][3];
            int t0 = mbase + drow, t1 = mbase + drow + 8;
            if (t0 < T) *(float2*)&slab[(size_t)t0 * 128 + col] = make_float2(d0, d1);
            if (t1 < T) *(float2*)&slab[(size_t)t1 * 128 + col] = make_float2(d2, d3);
        }
    }
    __threadfence();
    __syncthreads();
    if (tid == 0) {
        int old = atomicAdd(&g_cnt[mtile], 1);
        winflag = old & 1;                     // 2 arrivals per tile per launch
    }
    __syncthreads();
    if (!winflag) return;
    __threadfence();                           // acquire other CTA's partials

    // ---- fused epilogue: 16 warps x 2 tasks ----
    const int n0 = lane * 4;
    const float4 bj = *(const float4*)&b1[n0];
    const float4 w3 = *(const float4*)&W3[n0];
    const float4 w4 = *(const float4*)&W4[n0];
    const float4 w5 = *(const float4*)&W5[n0];
    const float4 w6 = *(const float4*)&W6[n0];
    const float B3 = b3[0], B4 = b4[0], B5 = b5[0], B6 = b6[0];

    #pragma unroll
    for (int it = 0; it < 2; it++) {
        int m = wid * 2 + it;
        int task = mbase + m;
        bool ok = (task < T);
        int rt = ok ? task : (T - 1);

        const float* gp = g_part + (size_t)rt * 128 + n0;
        float4 s0 = __ldcg((const float4*)gp);
        float4 s1 = __ldcg((const float4*)(gp + (size_t)MAXT * 128));
        float h0 = fmaxf(s0.x + s1.x + bj.x, 0.f);
        float h1 = fmaxf(s0.y + s1.y + bj.y, 0.f);
        float h2 = fmaxf(s0.z + s1.z + bj.z, 0.f);
        float h3 = fmaxf(s0.w + s1.w + bj.w, 0.f);
        float p3 = h0*w3.x + h1*w3.y + h2*w3.z + h3*w3.w;
        float p4 = h0*w4.x + h1*w4.y + h2*w4.z + h3*w4.w;
        float p5 = h0*w5.x + h1*w5.y + h2*w5.z + h3*w5.w;
        float p6 = h0*w6.x + h1*w6.y + h2*w6.z + h3*w6.w;

        float se = enode[(size_t)rt * 64 + lane] + enode[(size_t)rt * 64 + lane + 32];
        float sc = (lane < 4) ? ccl[rt * 4 + lane] : 0.0f;
        float sn = cnd[(size_t)rt * 32 + lane];

        #pragma unroll
        for (int off = 16; off; off >>= 1) {
            p3 += __shfl_xor_sync(0xffffffffu, p3, off);
            p4 += __shfl_xor_sync(0xffffffffu, p4, off);
            p5 += __shfl_xor_sync(0xffffffffu, p5, off);
            p6 += __shfl_xor_sync(0xffffffffu, p6, off);
            se += __shfl_xor_sync(0xffffffffu, se, off);
            sc += __shfl_xor_sync(0xffffffffu, sc, off);
            sn += __shfl_xor_sync(0xffffffffu, sn, off);
        }
        if (lane == 0 && ok) {
            float me = se * (1.0f / 64.0f);
            float ss = sc * sn;
            float y51 = 1.0f / (1.0f + expf(-(p3 * me + B3)));
            float y61 = p4 * me + B4;
            float y52 = 1.0f / (1.0f + expf(-(p5 * ss + B5)));
            float y62 = p6 * ss + B6;
            float p = y51 * y52;
            out[task] = (1.0f - p) * (-100.0f) + p * (y61 + y62);
        }
    }
}

// -----------------------------------------------------------------------------
extern "C" void kernel_launch(void* const* d_in, const int* in_sizes, int n_in,
                              void* d_out, int out_size) {
    const float* bb    = (const float*)d_in[2];
    const float* res   = (const float*)d_in[3];
    const float* fr    = (const float*)d_in[4];
    const float* estep = (const float*)d_in[5];
    const float* enode = (const float*)d_in[6];
    const float* ccl   = (const float*)d_in[7];
    const float* cnd   = (const float*)d_in[8];
    const float* W1    = (const float*)d_in[9];
    const float* b1    = (const float*)d_in[10];
    const float* W3    = (const float*)d_in[11];
    const float* b3    = (const float*)d_in[12];
    const float* W4    = (const float*)d_in[13];
    const float* b4    = (const float*)d_in[14];
    const float* W5    = (const float*)d_in[15];
    const float* b5    = (const float*)d_in[16];
    const float* W6    = (const float*)d_in[17];
    const float* b6    = (const float*)d_in[18];

    int T = in_sizes[2] / D_BB;
    if (T > MAXT) T = MAXT;

    static int cfg = 0;
    if (!cfg) {
        cudaFuncSetAttribute(critic_mma,
                             cudaFuncAttributeMaxDynamicSharedMemorySize,
                             SMEM_TOTAL);
        cfg = 1;
    }

    prep_B<<<120, 256>>>(W1);
    dim3 grid((T + 31) / 32, 2);
    critic_mma<<<grid, 512, SMEM_TOTAL>>>(
        bb, res, fr, estep, enode, ccl, cnd,
        b1, W3, b3, W4, b4, W5, b5, W6, b6, (float*)d_out, T);
}

// round 9
// speedup vs baseline: 1.1892x; 1.1892x over previous
#include <cuda_runtime.h>
#include <cuda_bf16.h>
#include <math.h>
#include <stdint.h>

#define D_BB 768
#define KPAD 960          // 160 feat(+pad) + 768 bb + 32 pad
#define CH   64           // k per chunk
#define NCH  15           // chunks
#define NSTG 4            // smem pipeline stages
#define BUFB 40960        // bytes per stage: Ah 4K | Al 4K | Bh 16K | Bl 16K
#define SMEM_TOTAL (NSTG * BUFB)

typedef unsigned long long u64;
typedef unsigned int       u32;

// ---- W1 pre-split to bf16 hi/lo, transposed [n][k] --------------------------
__device__ __align__(16) __nv_bfloat16 g_Bh[128 * KPAD];
__device__ __align__(16) __nv_bfloat16 g_Bl[128 * KPAD];

// ---- helpers -----------------------------------------------------------------
__device__ __forceinline__ u32 smem_u32(const void* p) {
    u32 a;
    asm("{ .reg .u64 t; cvta.to.shared.u64 t, %1; cvt.u32.u64 %0, t; }"
        : "=r"(a) : "l"(p));
    return a;
}
__device__ __forceinline__ u32 SWZ(u32 b) { return b ^ ((b >> 3) & 0x70); }

__device__ __forceinline__ u32 pack_bf2(float lo, float hi) {
    __nv_bfloat162 v = __floats2bfloat162_rn(lo, hi);
    return *(u32*)&v;
}
__device__ __forceinline__ float bfr(float x) {
    return __bfloat162float(__float2bfloat16_rn(x));
}

#define LDMX4(r, addr) \
    asm volatile("ldmatrix.sync.aligned.m8n8.x4.shared.b16 {%0,%1,%2,%3}, [%4];" \
        : "=r"((r)[0]), "=r"((r)[1]), "=r"((r)[2]), "=r"((r)[3]) : "r"(addr))

#define MMA16816(d, a, b0, b1) \
    asm volatile("mma.sync.aligned.m16n8k16.row.col.f32.bf16.bf16.f32 " \
        "{%0,%1,%2,%3}, {%4,%5,%6,%7}, {%8,%9}, {%0,%1,%2,%3};" \
        : "+f"((d)[0]), "+f"((d)[1]), "+f"((d)[2]), "+f"((d)[3]) \
        : "r"((a)[0]), "r"((a)[1]), "r"((a)[2]), "r"((a)[3]), "r"(b0), "r"(b1))

#define CPA16(dst, src) \
    asm volatile("cp.async.cg.shared.global [%0], [%1], 16;" \
        :: "r"(dst), "l"(src) : "memory")
#define CPA_COMMIT() asm volatile("cp.async.commit_group;" ::: "memory")
#define CPA_WAIT(n)  asm volatile("cp.async.wait_group %0;" :: "n"(n) : "memory")

#define STS64(r0, r1, sa) \
    asm volatile("st.shared.v2.b32 [%0], {%1, %2};" \
        :: "r"(sa), "r"(r0), "r"(r1) : "memory")

// -----------------------------------------------------------------------------
// Prep: W1 [918,128] fp32 -> g_Bh/g_Bl [128 n][960 k] bf16 split (row remap).
// -----------------------------------------------------------------------------
__global__ void prep_B(const float* __restrict__ W1) {
    int id = blockIdx.x * 256 + threadIdx.x;        // 128 n * 240 groups of 4
    if (id >= 128 * 240) return;
    int n  = id / 240;
    int k4 = (id % 240) * 4;
    u32 hw[2], lw[2];
    #pragma unroll
    for (int p = 0; p < 2; p++) {
        float v0 = 0.f, v1 = 0.f;
        int g0 = k4 + p * 2, g1 = g0 + 1;
        if (g0 < 150)                    v0 = W1[(size_t)g0 * 128 + n];
        else if (g0 >= 160 && g0 < 928)  v0 = W1[(size_t)(g0 - 10) * 128 + n];
        if (g1 < 150)                    v1 = W1[(size_t)g1 * 128 + n];
        else if (g1 >= 160 && g1 < 928)  v1 = W1[(size_t)(g1 - 10) * 128 + n];
        float h0 = bfr(v0), h1 = bfr(v1);
        hw[p] = pack_bf2(v0, v1);
        lw[p] = pack_bf2(v0 - h0, v1 - h1);
    }
    *(u64*)&g_Bh[(size_t)n * KPAD + k4] = (u64)hw[0] | ((u64)hw[1] << 32);
    *(u64*)&g_Bl[(size_t)n * KPAD + k4] = (u64)lw[0] | ((u64)lw[1] << 32);
}

// -----------------------------------------------------------------------------
// Fused kernel: grid = T/32 CTAs, 512 threads (16 warps: 2 M x 8 N tiles).
// 4-stage smem pipeline + A register prefetch + fragment double-buffering.
// -----------------------------------------------------------------------------
__global__ void __launch_bounds__(512, 1)
critic_mma(const float* __restrict__ bb,
           const float* __restrict__ res,   const float* __restrict__ fr,
           const float* __restrict__ estep, const float* __restrict__ enode,
           const float* __restrict__ ccl,   const float* __restrict__ cnd,
           const float* __restrict__ b1,
           const float* __restrict__ W3, const float* __restrict__ b3,
           const float* __restrict__ W4, const float* __restrict__ b4,
           const float* __restrict__ W5, const float* __restrict__ b5,
           const float* __restrict__ W6, const float* __restrict__ b6,
           float* __restrict__ out, int T)
{
    extern __shared__ __align__(16) char dsm[];
    const u32 sb = smem_u32(dsm);

    const int tid  = threadIdx.x;
    const int lane = tid & 31;
    const int wid  = tid >> 5;
    const int mbase = blockIdx.x * 32;

    const int m0w = (wid & 1) * 16;
    const int n0w = (wid >> 1) * 16;

    // ---- A loader mapping: thread -> (row, 4 consecutive k) ----
    const int ar = tid >> 4;
    const int ak = (tid & 15) * 4;
    int atask = mbase + ar; if (atask >= T) atask = T - 1;
    const float* bbrow = bb + (size_t)atask * D_BB;
    const u32 aoff = SWZ((u32)(ar * 128 + ak * 2));

    // ---- B loader mapping ----
    int brow[2], bseg[2]; u32 bdst[2];
    #pragma unroll
    for (int i = 0; i < 2; i++) {
        int id = tid + i * 512;
        brow[i] = id >> 3;
        bseg[i] = id & 7;
        bdst[i] = SWZ((u32)(brow[i] * 128 + bseg[i] * 16));
    }

    // ---- fragment address bases ----
    const u32 aRowByte = (u32)((m0w + (lane & 7) + ((lane >> 3) & 1) * 8) * 128
                               + (lane >> 4) * 16);
    const u32 bRowByte = (u32)((n0w + (lane >> 4) * 8 + (lane & 7)) * 128
                               + ((lane >> 3) & 1) * 16);

    float Da[2][4], Db[2][4], Dc[2][4];
    #pragma unroll
    for (int h = 0; h < 2; h++)
        #pragma unroll
        for (int j = 0; j < 4; j++) { Da[h][j] = 0.f; Db[h][j] = 0.f; Dc[h][j] = 0.f; }

    auto loadA_gen = [&](int c, float* x) {
        int g0 = c * CH + ak;
        if (g0 >= 160 && g0 + 4 <= 928) {
            float4 v = *(const float4*)(bbrow + (g0 - 160));
            x[0] = v.x; x[1] = v.y; x[2] = v.z; x[3] = v.w;
        } else {
            #pragma unroll
            for (int j = 0; j < 4; j++) {
                int gk = g0 + j;
                float v = 0.f;
                if (gk < 150) {
                    int nn = gk / 30, rem = gk - nn * 30;
                    int mm = rem / 6, oo = rem - mm * 6;
                    v = res[atask * 5 + nn] * fr[atask * 5 + mm] * estep[atask * 6 + oo];
                } else if (gk >= 160 && gk < 928) {
                    v = bbrow[gk - 160];
                }
                x[j] = v;
            }
        }
    };
    auto loadA_bb = [&](int c, float* x) {
        int g0 = c * CH + ak;
        if (g0 + 4 <= 928) {
            float4 v = *(const float4*)(bbrow + (g0 - 160));
            x[0] = v.x; x[1] = v.y; x[2] = v.z; x[3] = v.w;
        } else {
            x[0] = x[1] = x[2] = x[3] = 0.f;
        }
    };
    auto storeA = [&](int c, const float* x) {
        const u32 base = sb + (u32)(c % NSTG) * BUFB;
        float h0 = bfr(x[0]), h1 = bfr(x[1]), h2 = bfr(x[2]), h3 = bfr(x[3]);
        STS64(pack_bf2(x[0], x[1]), pack_bf2(x[2], x[3]), base + aoff);
        STS64(pack_bf2(x[0] - h0, x[1] - h1), pack_bf2(x[2] - h2, x[3] - h3),
              base + 4096 + aoff);
    };
    auto issueB = [&](int c) {
        const u32 base = sb + (u32)(c % NSTG) * BUFB;
        #pragma unroll
        for (int i = 0; i < 2; i++) {
            const size_t so = (size_t)brow[i] * KPAD + c * CH + bseg[i] * 8;
            CPA16(base + 8192  + bdst[i], g_Bh + so);
            CPA16(base + 24576 + bdst[i], g_Bl + so);
        }
    };

    // fragment double buffers
    u32 fa_h[2][4], fa_l[2][4], fb_h[2][4], fb_l[2][4];

    auto loadFrag = [&](int c, int ks, int buf) {
        const u32 base = sb + (u32)(c % NSTG) * BUFB;
        const u32 ao = SWZ(aRowByte + ks * 32);
        const u32 bo = SWZ(bRowByte + ks * 32);
        LDMX4(fa_h[buf], base + ao);
        LDMX4(fb_h[buf], base + 8192 + bo);
        LDMX4(fa_l[buf], base + 4096 + ao);
        LDMX4(fb_l[buf], base + 24576 + bo);
    };
    auto mmas = [&](int buf) {
        // consecutive MMAs hit different accumulators (no same-acc RAW chain)
        MMA16816(Da[0], fa_h[buf], fb_h[buf][0], fb_h[buf][1]);
        MMA16816(Da[1], fa_h[buf], fb_h[buf][2], fb_h[buf][3]);
        MMA16816(Db[0], fa_h[buf], fb_l[buf][0], fb_l[buf][1]);
        MMA16816(Db[1], fa_h[buf], fb_l[buf][2], fb_l[buf][3]);
        MMA16816(Dc[0], fa_l[buf], fb_h[buf][0], fb_h[buf][1]);
        MMA16816(Dc[1], fa_l[buf], fb_h[buf][2], fb_h[buf][3]);
    };
    auto compute = [&](int c) {
        loadFrag(c, 0, 0);
        loadFrag(c, 1, 1);
        mmas(0);
        loadFrag(c, 2, 0);
        mmas(1);
        loadFrag(c, 3, 1);
        mmas(0);
        mmas(1);
    };

    // ---- prologue: fill stages 0..2, prefetch A(3) into regs ----
    float xp0[4], xp1[4], xp2[4];
    loadA_gen(0, xp0); loadA_gen(1, xp1); loadA_gen(2, xp2);
    storeA(0, xp0); issueB(0); CPA_COMMIT();
    storeA(1, xp1); issueB(1); CPA_COMMIT();
    storeA(2, xp2); issueB(2); CPA_COMMIT();
    float xcur[4];
    loadA_bb(3, xcur);
    CPA_WAIT(2);            // stage 0 B complete
    __syncthreads();

    // ---- main loop: 1 sync/chunk; A staged from regs; LDG 1 chunk ahead ----
    for (int c = 0; c < NCH; c++) {
        compute(c);
        if (c + 3 < NCH) {
            storeA(c + 3, xcur);
            if (c + 4 < NCH) loadA_bb(c + 4, xcur);
            issueB(c + 3); CPA_COMMIT();
            CPA_WAIT(2);
        } else if (c + 2 < NCH) {
            CPA_WAIT(1);
        } else if (c + 1 < NCH) {
            CPA_WAIT(0);
        }
        __syncthreads();
    }

    // ---- combine accumulator sets, stage to smem ----
    float* hsm = (float*)dsm;               // [32][132]
    const int drow = m0w + (lane >> 2);
    #pragma unroll
    for (int h = 0; h < 2; h++) {
        int col = n0w + h * 8 + 2 * (lane & 3);
        float d0 = Da[h][0] + Db[h][0] + Dc[h][0];
        float d1 = Da[h][1] + Db[h][1] + Dc[h][1];
        float d2 = Da[h][2] + Db[h][2] + Dc[h][2];
        float d3 = Da[h][3] + Db[h][3] + Dc[h][3];
        *(float2*)&hsm[drow * 132 + col]       = make_float2(d0, d1);
        *(float2*)&hsm[(drow + 8) * 132 + col] = make_float2(d2, d3);
    }
    __syncthreads();

    // ---- per-task epilogue: 16 warps x 2 tasks ----
    const int n0 = lane * 4;
    const float4 bj = *(const float4*)&b1[n0];
    const float4 w3 = *(const float4*)&W3[n0];
    const float4 w4 = *(const float4*)&W4[n0];
    const float4 w5 = *(const float4*)&W5[n0];
    const float4 w6 = *(const float4*)&W6[n0];
    const float B3 = b3[0], B4 = b4[0], B5 = b5[0], B6 = b6[0];

    #pragma unroll
    for (int it = 0; it < 2; it++) {
        int m = wid * 2 + it;
        int task = mbase + m;
        bool ok = (task < T);
        int rt = ok ? task : (T - 1);

        float4 s = *(const float4*)&hsm[m * 132 + n0];
        float h0 = fmaxf(s.x + bj.x, 0.f), h1 = fmaxf(s.y + bj.y, 0.f);
        float h2 = fmaxf(s.z + bj.z, 0.f), h3 = fmaxf(s.w + bj.w, 0.f);
        float p3 = h0*w3.x + h1*w3.y + h2*w3.z + h3*w3.w;
        float p4 = h0*w4.x + h1*w4.y + h2*w4.z + h3*w4.w;
        float p5 = h0*w5.x + h1*w5.y + h2*w5.z + h3*w5.w;
        float p6 = h0*w6.x + h1*w6.y + h2*w6.z + h3*w6.w;

        float se = enode[(size_t)rt * 64 + lane] + enode[(size_t)rt * 64 + lane + 32];
        float sc = (lane < 4) ? ccl[rt * 4 + lane] : 0.0f;
        float sn = cnd[(size_t)rt * 32 + lane];

        #pragma unroll
        for (int off = 16; off; off >>= 1) {
            p3 += __shfl_xor_sync(0xffffffffu, p3, off);
            p4 += __shfl_xor_sync(0xffffffffu, p4, off);
            p5 += __shfl_xor_sync(0xffffffffu, p5, off);
            p6 += __shfl_xor_sync(0xffffffffu, p6, off);
            se += __shfl_xor_sync(0xffffffffu, se, off);
            sc += __shfl_xor_sync(0xffffffffu, sc, off);
            sn += __shfl_xor_sync(0xffffffffu, sn, off);
        }
        if (lane == 0 && ok) {
            float me = se * (1.0f / 64.0f);
            float ss = sc * sn;
            float y51 = 1.0f / (1.0f + expf(-(p3 * me + B3)));
            float y61 = p4 * me + B4;
            float y52 = 1.0f / (1.0f + expf(-(p5 * ss + B5)));
            float y62 = p6 * ss + B6;
            float p = y51 * y52;
            out[task] = (1.0f - p) * (-100.0f) + p * (y61 + y62);
        }
    }
}

// -----------------------------------------------------------------------------
extern "C" void kernel_launch(void* const* d_in, const int* in_sizes, int n_in,
                              void* d_out, int out_size) {
    const float* bb    = (const float*)d_in[2];
    const float* res   = (const float*)d_in[3];
    const float* fr    = (const float*)d_in[4];
    const float* estep = (const float*)d_in[5];
    const float* enode = (const float*)d_in[6];
    const float* ccl   = (const float*)d_in[7];
    const float* cnd   = (const float*)d_in[8];
    const float* W1    = (const float*)d_in[9];
    const float* b1    = (const float*)d_in[10];
    const float* W3    = (const float*)d_in[11];
    const float* b3    = (const float*)d_in[12];
    const float* W4    = (const float*)d_in[13];
    const float* b4    = (const float*)d_in[14];
    const float* W5    = (const float*)d_in[15];
    const float* b5    = (const float*)d_in[16];
    const float* W6    = (const float*)d_in[17];
    const float* b6    = (const float*)d_in[18];

    int T = in_sizes[2] / D_BB;

    static int cfg = 0;
    if (!cfg) {
        cudaFuncSetAttribute(critic_mma,
                             cudaFuncAttributeMaxDynamicSharedMemorySize,
                             SMEM_TOTAL);
        cfg = 1;
    }

    prep_B<<<120, 256>>>(W1);
    critic_mma<<<(T + 31) / 32, 512, SMEM_TOTAL>>>(
        bb, res, fr, estep, enode, ccl, cnd,
        b1, W3, b3, W4, b4, W5, b5, W6, b6, (float*)d_out, T);
}